// round 16
// baseline (speedup 1.0000x reference)
#include <cuda_runtime.h>
#include <cstdint>

#define NQ    4
#define CIN   64
#define HH    64
#define WW    64
#define OUTC  128
#define TH    16
#define TW    16
#define NTHR  128
#define HALO_H (TH + 2)
#define HALO_W (TW + 2)
#define HALO_N (HALO_H * HALO_W)   // 324

typedef unsigned long long ull;

#define FMA2(acc, a, b) \
    asm("fma.rn.f32x2 %0, %1, %2, %0;" : "+l"(acc) : "l"(a), "l"(b))
#define FMA2N(d, a, b, c) \
    asm("fma.rn.f32x2 %0, %1, %2, %3;" : "=l"(d) : "l"(a), "l"(b), "l"(c))
#define MUL2(d, a, b) \
    asm("mul.rn.f32x2 %0, %1, %2;" : "=l"(d) : "l"(a), "l"(b))
#define PACK2(d, lo, hi) \
    asm("mov.b64 %0, {%1, %2};" : "=l"(d) : "f"(lo), "f"(hi))
#define UNPACK2(lo, hi, s) \
    asm("mov.b64 {%0, %1}, %2;" : "=f"(lo), "=f"(hi) : "l"(s))
// Explicit 8-byte shared load (kept as a distinct instruction; not fused to .128)
#define LDS64(d, addr) \
    asm("ld.shared.b64 %0, [%1];" : "=l"(d) : "r"(addr))

__device__ __forceinline__ uint32_t smem_u32(const void* p) {
    uint32_t a;
    asm("{ .reg .u64 t; cvta.to.shared.u64 t, %1; cvt.u32.u64 %0, t; }"
        : "=r"(a) : "l"(p));
    return a;
}

// Dual-pixel packed 4-qubit circuit: pixel A in lane .x, pixel B in lane .y.
__device__ __forceinline__ void quantum_ez_pair(
    const ull* __restrict__ sgu3, const ull* __restrict__ sgcu,
    float aA0, float aA1, float aA2, float aA3,
    float bB0, float bB1, float bB2, float bB3,
    float4* eA, float4* eB)
{
    ull neg1, one;
    { float n = -1.f, p = 1.f; PACK2(neg1, n, n); PACK2(one, p, p); }

    float aA[4] = {aA0, aA1, aA2, aA3};
    float aB[4] = {bB0, bB1, bB2, bB3};

    ull S[4][4], SiN[4][2];
    #pragma unroll
    for (int q = 0; q < 4; ++q) {
        float sA, cA, sB, cB;
        __sincosf(0.5f * aA[q], &sA, &cA);
        __sincosf(0.5f * aB[q], &sB, &cB);
        ull ctp, stp;
        PACK2(ctp, cA, cB);
        PACK2(stp, sA, sB);
        const ull* m = sgu3 + q * 8;
        ull t1;
        MUL2(t1, m[2], stp); FMA2N(S[q][0], m[0], ctp, t1);
        MUL2(t1, m[3], stp); FMA2N(S[q][1], m[1], ctp, t1);
        MUL2(t1, m[6], stp); FMA2N(S[q][2], m[4], ctp, t1);
        MUL2(t1, m[7], stp); FMA2N(S[q][3], m[5], ctp, t1);
        MUL2(SiN[q][0], S[q][1], neg1);
        MUL2(SiN[q][1], S[q][3], neg1);
    }

    ull q01r[4], q01i[4], q23r[4], q23i[4], q01iN[4];
    #pragma unroll
    for (int i0 = 0; i0 < 2; ++i0)
        #pragma unroll
        for (int i1 = 0; i1 < 2; ++i1) {
            const int k = i0 * 2 + i1;
            ull t;
            MUL2(t, S[0][i0*2], S[1][i1*2]);
            FMA2N(q01r[k], SiN[0][i0], S[1][i1*2+1], t);
            MUL2(t, S[0][i0*2], S[1][i1*2+1]);
            FMA2N(q01i[k], S[0][i0*2+1], S[1][i1*2], t);
            MUL2(t, S[2][i0*2], S[3][i1*2]);
            FMA2N(q23r[k], SiN[2][i0], S[3][i1*2+1], t);
            MUL2(t, S[2][i0*2], S[3][i1*2+1]);
            FMA2N(q23i[k], S[2][i0*2+1], S[3][i1*2], t);
        }
    #pragma unroll
    for (int k = 0; k < 4; ++k) MUL2(q01iN[k], q01i[k], neg1);

    ull pr[16], pi[16];
    #pragma unroll
    for (int u = 0; u < 4; ++u)
        #pragma unroll
        for (int v = 0; v < 4; ++v) {
            ull t;
            MUL2(t, q01r[u], q23r[v]);
            FMA2N(pr[u * 4 + v], q01iN[u], q23i[v], t);
            MUL2(t, q01r[u], q23i[v]);
            FMA2N(pi[u * 4 + v], q01i[u], q23r[v], t);
        }

    #pragma unroll
    for (int g = 0; g < 4; ++g) {
        const ull* U = sgcu + g * 12;
        ull u00r = U[0], u00i = U[1], u00iN = U[2];
        ull u01r = U[3], u01i = U[4], u01iN = U[5];
        ull u10r = U[6], u10i = U[7], u10iN = U[8];
        ull u11r = U[9], u11i = U[10], u11iN = U[11];
        const int bc = 8 >> g;
        const int bt = 8 >> ((g + 1) & 3);
        #pragma unroll
        for (int i = 0; i < 16; ++i) {
            if ((i & bc) && !(i & bt)) {
                const int j = i | bt;
                ull x0r = pr[i], x0i = pi[i], x1r = pr[j], x1i = pi[j];
                ull npr, npi, mpr, mpi;
                MUL2(npr, u00r, x0r); FMA2(npr, u00iN, x0i);
                FMA2(npr, u01r, x1r); FMA2(npr, u01iN, x1i);
                MUL2(npi, u00r, x0i); FMA2(npi, u00i, x0r);
                FMA2(npi, u01r, x1i); FMA2(npi, u01i, x1r);
                MUL2(mpr, u10r, x0r); FMA2(mpr, u10iN, x0i);
                FMA2(mpr, u11r, x1r); FMA2(mpr, u11iN, x1i);
                MUL2(mpi, u10r, x0i); FMA2(mpi, u10i, x0r);
                FMA2(mpi, u11r, x1i); FMA2(mpi, u11i, x1r);
                pr[i] = npr; pi[i] = npi; pr[j] = mpr; pi[j] = mpi;
            }
        }
    }

    ull e0, e1, e2, e3;
    { float z = 0.f; PACK2(e0, z, z); PACK2(e1, z, z); PACK2(e2, z, z); PACK2(e3, z, z); }
    #pragma unroll
    for (int i = 0; i < 16; ++i) {
        ull pp;
        MUL2(pp, pr[i], pr[i]);
        FMA2(pp, pi[i], pi[i]);
        FMA2(e0, pp, (i & 8) ? neg1 : one);
        FMA2(e1, pp, (i & 4) ? neg1 : one);
        FMA2(e2, pp, (i & 2) ? neg1 : one);
        FMA2(e3, pp, (i & 1) ? neg1 : one);
    }
    float fa, fb;
    UNPACK2(fa, fb, e0); eA->x = fa; eB->x = fb;
    UNPACK2(fa, fb, e1); eA->y = fa; eB->y = fb;
    UNPACK2(fa, fb, e2); eA->z = fa; eB->z = fb;
    UNPACK2(fa, fb, e3); eA->w = fa; eB->w = fb;
}

__global__ __launch_bounds__(NTHR, 2)
void qconv_kernel(const float* __restrict__ x,     // (16,64,64,64)
                  const float* __restrict__ fc1w,  // (4,576)
                  const float* __restrict__ fc1b,  // (4,)
                  const float* __restrict__ u3p,   // (4,3)
                  const float* __restrict__ cu3p,  // (4,3)
                  const float* __restrict__ fcw,   // (128,4)
                  const float* __restrict__ fcb,   // (128,)
                  float* __restrict__ out)         // (16,4096,128) flat
{
    __shared__ float4 wq[576];            // packed conv weights (f32x2 pairs)
    __shared__ float4 xs4[2][2][HALO_N];  // [buf][chan-group][pos] 4 channels/float4
    __shared__ float4 ezd[TH * TW * 2];   // duplicated <Z>
    __shared__ ull    sgu3[32];
    __shared__ ull    sgcu[48];

    const int t  = threadIdx.x;
    const int b  = blockIdx.z;
    const int h0 = blockIdx.y * TH;
    const int w0 = blockIdx.x * TW;

    // ---- per-block setup ----
    if (t < 8) {
        const float* p = (t < 4) ? (u3p + t * 3) : (cu3p + (t - 4) * 3);
        float th = p[0], ph = p[1], la = p[2];
        float st, ct;   __sincosf(0.5f * th, &st, &ct);
        float sl, cl;   __sincosf(la, &sl, &cl);
        float sp, cp;   __sincosf(ph, &sp, &cp);
        float spl, cpl; __sincosf(ph + la, &spl, &cpl);
        float o0 = ct,        o1 = 0.f;
        float o2 = -cl * st,  o3 = -sl * st;
        float o4 = cp * st,   o5 = sp * st;
        float o6 = cpl * ct,  o7 = spl * ct;
        ull tmp;
        if (t < 4) {
            ull* d = sgu3 + t * 8;
            PACK2(tmp, o0, o0); d[0] = tmp;  PACK2(tmp, o1, o1); d[1] = tmp;
            PACK2(tmp, o2, o2); d[2] = tmp;  PACK2(tmp, o3, o3); d[3] = tmp;
            PACK2(tmp, o4, o4); d[4] = tmp;  PACK2(tmp, o5, o5); d[5] = tmp;
            PACK2(tmp, o6, o6); d[6] = tmp;  PACK2(tmp, o7, o7); d[7] = tmp;
        } else {
            ull* d = sgcu + (t - 4) * 12;
            float n1 = -o1, n3 = -o3, n5 = -o5, n7 = -o7;
            PACK2(tmp, o0, o0); d[0]  = tmp;  PACK2(tmp, o1, o1); d[1]  = tmp;
            PACK2(tmp, n1, n1); d[2]  = tmp;  PACK2(tmp, o2, o2); d[3]  = tmp;
            PACK2(tmp, o3, o3); d[4]  = tmp;  PACK2(tmp, n3, n3); d[5]  = tmp;
            PACK2(tmp, o4, o4); d[6]  = tmp;  PACK2(tmp, o5, o5); d[7]  = tmp;
            PACK2(tmp, n5, n5); d[8]  = tmp;  PACK2(tmp, o6, o6); d[9]  = tmp;
            PACK2(tmp, o7, o7); d[10] = tmp;  PACK2(tmp, n7, n7); d[11] = tmp;
        }
    }
    #pragma unroll
    for (int f = t; f < 576; f += NTHR) {
        int hh  = f & 1;
        int p   = (f >> 1) & 3;
        int tap = (f >> 3) % 9;
        int s   = f / 72;
        int c0  = s * 8 + 2 * p;
        int oa  = 2 * hh, ob = 2 * hh + 1;
        wq[f] = make_float4(fc1w[oa * 576 + c0 * 9 + tap],
                            fc1w[oa * 576 + (c0 + 1) * 9 + tap],
                            fc1w[ob * 576 + c0 * 9 + tap],
                            fc1w[ob * 576 + (c0 + 1) * 9 + tap]);
    }

    const int ty = t >> 4;   // 0..7  (handles pixel rows 2ty, 2ty+1)
    const int tx = t & 15;   // 0..15
    const int by = h0 - 1, bx = w0 - 1;

    // ---- channel-invariant halo staging: 3 slots/thread over 324 positions ----
    const int i0 = t, i1 = t + NTHR, i2 = t + 2 * NTHR;
    const bool has2 = (i2 < HALO_N);
    const int r0 = i0 / HALO_W, c0s = i0 - r0 * HALO_W;
    const int r1 = i1 / HALO_W, c1s = i1 - r1 * HALO_W;
    const int r2 = has2 ? i2 / HALO_W : 0, c2s = has2 ? (i2 - r2 * HALO_W) : 0;

    int gy, gx;
    gy = by + r0; gx = bx + c0s;
    const bool va0 = (unsigned)gy < (unsigned)HH && (unsigned)gx < (unsigned)WW;
    const float* cur0 = x + ((size_t)b * CIN) * (HH * WW) + (va0 ? gy * WW + gx : 0);
    gy = by + r1; gx = bx + c1s;
    const bool va1 = (unsigned)gy < (unsigned)HH && (unsigned)gx < (unsigned)WW;
    const float* cur1 = x + ((size_t)b * CIN) * (HH * WW) + (va1 ? gy * WW + gx : 0);
    gy = by + r2; gx = bx + c2s;
    const bool va2 = has2 && (unsigned)gy < (unsigned)HH && (unsigned)gx < (unsigned)WW;
    const float* cur2 = x + ((size_t)b * CIN) * (HH * WW) + (va2 ? gy * WW + gx : 0);

    float v0[8], v1[8], v2[8];
    #pragma unroll
    for (int k = 0; k < 8; ++k) v0[k] = va0 ? cur0[k * (HH * WW)] : 0.f;
    #pragma unroll
    for (int k = 0; k < 8; ++k) v1[k] = va1 ? cur1[k * (HH * WW)] : 0.f;
    #pragma unroll
    for (int k = 0; k < 8; ++k) v2[k] = va2 ? cur2[k * (HH * WW)] : 0.f;
    cur0 += 8 * HH * WW; cur1 += 8 * HH * WW; cur2 += 8 * HH * WW;

    // 8 packed accumulators: A = pixel row 2ty, B = pixel row 2ty+1.
    ull A0, A1, A2, A3, B0, B1, B2, B3;
    {
        float z = 0.f;
        float b0 = fc1b[0], b1 = fc1b[1], b2 = fc1b[2], b3 = fc1b[3];
        PACK2(A0, b0, z); PACK2(A1, b1, z); PACK2(A2, b2, z); PACK2(A3, b3, z);
        PACK2(B0, b0, z); PACK2(B1, b1, z); PACK2(B2, b2, z); PACK2(B3, b3, z);
    }

    const int hbase = (2 * ty) * HALO_W + tx;
    const uint32_t xsa[2][2] = {
        { smem_u32(xs4[0][0]), smem_u32(xs4[0][1]) },
        { smem_u32(xs4[1][0]), smem_u32(xs4[1][1]) },
    };

    // Double-buffered, ONE barrier per stage: STS(s) -> LDG(s+1) -> bar -> compute(s)
    for (int s = 0; s < 8; ++s) {
        {
            float4* d0 = xs4[s & 1][0];
            float4* d1 = xs4[s & 1][1];
            d0[i0] = make_float4(v0[0], v0[1], v0[2], v0[3]);
            d1[i0] = make_float4(v0[4], v0[5], v0[6], v0[7]);
            d0[i1] = make_float4(v1[0], v1[1], v1[2], v1[3]);
            d1[i1] = make_float4(v1[4], v1[5], v1[6], v1[7]);
            if (has2) {
                d0[i2] = make_float4(v2[0], v2[1], v2[2], v2[3]);
                d1[i2] = make_float4(v2[4], v2[5], v2[6], v2[7]);
            }
        }
        if (s < 7) {
            #pragma unroll
            for (int k = 0; k < 8; ++k) v0[k] = va0 ? cur0[k * (HH * WW)] : 0.f;
            #pragma unroll
            for (int k = 0; k < 8; ++k) v1[k] = va1 ? cur1[k * (HH * WW)] : 0.f;
            #pragma unroll
            for (int k = 0; k < 8; ++k) v2[k] = va2 ? cur2[k * (HH * WW)] : 0.f;
            cur0 += 8 * HH * WW; cur1 += 8 * HH * WW; cur2 += 8 * HH * WW;
        }
        __syncthreads();

        const uint32_t xg0a = xsa[s & 1][0];
        const uint32_t xg1a = xsa[s & 1][1];
        const ulonglong2* wp = (const ulonglong2*)(wq + s * 72);

        #pragma unroll
        for (int dj = 0; dj < 3; ++dj) {
            // Two LDS.64 per position instead of one LDS.128: same bytes/
            // wavefronts but spread across instructions (replay-rate fix).
            ull xlo0[4], xlo1[4], xhi0[4], xhi1[4];
            #pragma unroll
            for (int r = 0; r < 4; ++r) {
                const uint32_t a0 = xg0a + (uint32_t)(hbase + dj + r * HALO_W) * 16u;
                LDS64(xlo0[r], a0);
                LDS64(xlo1[r], a0 + 8u);
            }
            #pragma unroll
            for (int r = 0; r < 4; ++r) {
                const uint32_t a1 = xg1a + (uint32_t)(hbase + dj + r * HALO_W) * 16u;
                LDS64(xhi0[r], a1);
                LDS64(xhi1[r], a1 + 8u);
            }
            #pragma unroll
            for (int di = 0; di < 3; ++di) {
                const ulonglong2* wt = wp + (di * 3 + dj) * 8;
                ulonglong2 w0 = wt[0], w1 = wt[1], w2 = wt[2], w3 = wt[3];
                ulonglong2 w4 = wt[4], w5 = wt[5], w6 = wt[6], w7 = wt[7];
                FMA2(A0, xlo0[di], w0.x); FMA2(A1, xlo0[di], w0.y);
                FMA2(A2, xlo0[di], w1.x); FMA2(A3, xlo0[di], w1.y);
                FMA2(B0, xlo0[di+1], w0.x); FMA2(B1, xlo0[di+1], w0.y);
                FMA2(B2, xlo0[di+1], w1.x); FMA2(B3, xlo0[di+1], w1.y);
                FMA2(A0, xlo1[di], w2.x); FMA2(A1, xlo1[di], w2.y);
                FMA2(A2, xlo1[di], w3.x); FMA2(A3, xlo1[di], w3.y);
                FMA2(B0, xlo1[di+1], w2.x); FMA2(B1, xlo1[di+1], w2.y);
                FMA2(B2, xlo1[di+1], w3.x); FMA2(B3, xlo1[di+1], w3.y);
                FMA2(A0, xhi0[di], w4.x); FMA2(A1, xhi0[di], w4.y);
                FMA2(A2, xhi0[di], w5.x); FMA2(A3, xhi0[di], w5.y);
                FMA2(B0, xhi0[di+1], w4.x); FMA2(B1, xhi0[di+1], w4.y);
                FMA2(B2, xhi0[di+1], w5.x); FMA2(B3, xhi0[di+1], w5.y);
                FMA2(A0, xhi1[di], w6.x); FMA2(A1, xhi1[di], w6.y);
                FMA2(A2, xhi1[di], w7.x); FMA2(A3, xhi1[di], w7.y);
                FMA2(B0, xhi1[di+1], w6.x); FMA2(B1, xhi1[di+1], w6.y);
                FMA2(B2, xhi1[di+1], w7.x); FMA2(B3, xhi1[di+1], w7.y);
            }
        }
    }

    // Reduce packed accumulators -> angles; run BOTH pixels' circuits packed.
    {
        float lo, hi;
        float aA0, aA1, aA2, aA3, bB0, bB1, bB2, bB3;
        UNPACK2(lo, hi, A0); aA0 = lo + hi;
        UNPACK2(lo, hi, A1); aA1 = lo + hi;
        UNPACK2(lo, hi, A2); aA2 = lo + hi;
        UNPACK2(lo, hi, A3); aA3 = lo + hi;
        UNPACK2(lo, hi, B0); bB0 = lo + hi;
        UNPACK2(lo, hi, B1); bB1 = lo + hi;
        UNPACK2(lo, hi, B2); bB2 = lo + hi;
        UNPACK2(lo, hi, B3); bB3 = lo + hi;
        float4 eA, eB;
        quantum_ez_pair(sgu3, sgcu, aA0, aA1, aA2, aA3, bB0, bB1, bB2, bB3,
                        &eA, &eB);
        int lpA = (2 * ty) * TW + tx;
        ezd[lpA * 2 + 0] = make_float4(eA.x, eA.x, eA.y, eA.y);
        ezd[lpA * 2 + 1] = make_float4(eA.z, eA.z, eA.w, eA.w);
        int lpB = (2 * ty + 1) * TW + tx;
        ezd[lpB * 2 + 0] = make_float4(eB.x, eB.x, eB.y, eB.y);
        ezd[lpB * 2 + 1] = make_float4(eB.z, eB.z, eB.w, eB.w);
    }
    __syncthreads();

    // ---------------- coalesced FC epilogue (f32x2-packed) ----------------
    const int lane = t & 31;
    const int wi   = t >> 5;
    const float4* fw4 = (const float4*)fcw;
    float4 fr0 = fw4[4 * lane + 0];
    float4 fr1 = fw4[4 * lane + 1];
    float4 fr2 = fw4[4 * lane + 2];
    float4 fr3 = fw4[4 * lane + 3];
    float4 bb4 = ((const float4*)fcb)[lane];

    ull w01k0, w01k1, w01k2, w01k3;
    ull w23k0, w23k1, w23k2, w23k3;
    ull bias01, bias23;
    PACK2(w01k0, fr0.x, fr1.x); PACK2(w01k1, fr0.y, fr1.y);
    PACK2(w01k2, fr0.z, fr1.z); PACK2(w01k3, fr0.w, fr1.w);
    PACK2(w23k0, fr2.x, fr3.x); PACK2(w23k1, fr2.y, fr3.y);
    PACK2(w23k2, fr2.z, fr3.z); PACK2(w23k3, fr2.w, fr3.w);
    PACK2(bias01, bb4.x, bb4.y); PACK2(bias23, bb4.z, bb4.w);

    const ulonglong2* ezp = (const ulonglong2*)ezd;
    ulonglong2* ob = (ulonglong2*)out + (size_t)b * 4096 * 32;
    #pragma unroll 4
    for (int j = 0; j < 64; ++j) {
        const int lp = wi * 64 + j;
        ulonglong2 e01 = ezp[lp * 2 + 0];
        ulonglong2 e23 = ezp[lp * 2 + 1];
        ull acc01, acc23;
        FMA2N(acc01, w01k0, e01.x, bias01);
        FMA2N(acc23, w23k0, e01.x, bias23);
        FMA2(acc01, w01k1, e01.y); FMA2(acc23, w23k1, e01.y);
        FMA2(acc01, w01k2, e23.x); FMA2(acc23, w23k2, e23.x);
        FMA2(acc01, w01k3, e23.y); FMA2(acc23, w23k3, e23.y);
        const int py = h0 + (lp >> 4);
        const int px = w0 + (lp & 15);
        ulonglong2 o2; o2.x = acc01; o2.y = acc23;
        ob[(size_t)(py * WW + px) * 32 + lane] = o2;
    }
}

extern "C" void kernel_launch(void* const* d_in, const int* in_sizes, int n_in,
                              void* d_out, int out_size)
{
    (void)in_sizes; (void)n_in; (void)out_size;
    const float* x    = (const float*)d_in[0];
    const float* fc1w = (const float*)d_in[1];
    const float* fc1b = (const float*)d_in[2];
    const float* u3p  = (const float*)d_in[3];
    const float* cu3p = (const float*)d_in[4];
    const float* fcw  = (const float*)d_in[5];
    const float* fcb  = (const float*)d_in[6];
    float* out = (float*)d_out;

    dim3 grid(WW / TW, HH / TH, 16);
    qconv_kernel<<<grid, NTHR>>>(x, fc1w, fc1b, u3p, cu3p, fcw, fcb, out);
}

// round 17
// speedup vs baseline: 1.1882x; 1.1882x over previous
#include <cuda_runtime.h>

#define NQ    4
#define CIN   64
#define HH    64
#define WW    64
#define OUTC  128
#define TH    16
#define TW    16
#define NTHR  128
#define HALO_H (TH + 2)
#define HALO_W (TW + 2)
#define HALO_N (HALO_H * HALO_W)   // 324

#define FMA2(acc, a, b) \
    asm("fma.rn.f32x2 %0, %1, %2, %0;" : "+l"(acc) : "l"(a), "l"(b))
#define FMA2N(d, a, b, c) \
    asm("fma.rn.f32x2 %0, %1, %2, %3;" : "=l"(d) : "l"(a), "l"(b), "l"(c))
#define PACK2(d, lo, hi) \
    asm("mov.b64 %0, {%1, %2};" : "=l"(d) : "f"(lo), "f"(hi))

// Full 4-qubit circuit from the 4 angles -> <Z> per wire. Gates in smem.
__device__ __forceinline__ float4 quantum_ez(const float* __restrict__ sg,
                                             float a0, float a1, float a2, float a3)
{
    float S[NQ][4];
    float angs[NQ] = {a0, a1, a2, a3};
    #pragma unroll
    for (int q = 0; q < NQ; ++q) {
        float st, ct;
        __sincosf(0.5f * angs[q], &st, &ct);
        const float* m = sg + q * 8;
        S[q][0] = m[0] * ct + m[2] * st;
        S[q][1] = m[1] * ct + m[3] * st;
        S[q][2] = m[4] * ct + m[6] * st;
        S[q][3] = m[5] * ct + m[7] * st;
    }

    float q01r[4], q01i[4], q23r[4], q23i[4];
    #pragma unroll
    for (int i0 = 0; i0 < 2; ++i0)
        #pragma unroll
        for (int i1 = 0; i1 < 2; ++i1) {
            float xr = S[0][i0 * 2], xi = S[0][i0 * 2 + 1];
            float yr = S[1][i1 * 2], yi = S[1][i1 * 2 + 1];
            q01r[i0 * 2 + i1] = xr * yr - xi * yi;
            q01i[i0 * 2 + i1] = xr * yi + xi * yr;
            xr = S[2][i0 * 2]; xi = S[2][i0 * 2 + 1];
            yr = S[3][i1 * 2]; yi = S[3][i1 * 2 + 1];
            q23r[i0 * 2 + i1] = xr * yr - xi * yi;
            q23i[i0 * 2 + i1] = xr * yi + xi * yr;
        }

    float pr[16], pi[16];
    #pragma unroll
    for (int u = 0; u < 4; ++u)
        #pragma unroll
        for (int v = 0; v < 4; ++v) {
            pr[u * 4 + v] = q01r[u] * q23r[v] - q01i[u] * q23i[v];
            pi[u * 4 + v] = q01r[u] * q23i[v] + q01i[u] * q23r[v];
        }

    #pragma unroll
    for (int g = 0; g < 4; ++g) {
        const float* U = sg + 32 + g * 8;
        float u00r = U[0], u00i = U[1], u01r = U[2], u01i = U[3];
        float u10r = U[4], u10i = U[5], u11r = U[6], u11i = U[7];
        const int bc = 8 >> g;
        const int bt = 8 >> ((g + 1) & 3);
        #pragma unroll
        for (int i = 0; i < 16; ++i) {
            if ((i & bc) && !(i & bt)) {
                const int j = i | bt;
                float x0r = pr[i], x0i = pi[i], x1r = pr[j], x1i = pi[j];
                pr[i] = u00r * x0r - u00i * x0i + u01r * x1r - u01i * x1i;
                pi[i] = u00r * x0i + u00i * x0r + u01r * x1i + u01i * x1r;
                pr[j] = u10r * x0r - u10i * x0i + u11r * x1r - u11i * x1i;
                pi[j] = u10r * x0i + u10i * x0r + u11r * x1i + u11i * x1r;
            }
        }
    }

    float e0 = 0.f, e1 = 0.f, e2 = 0.f, e3 = 0.f;
    #pragma unroll
    for (int i = 0; i < 16; ++i) {
        float pp = pr[i] * pr[i] + pi[i] * pi[i];
        e0 += (i & 8) ? -pp : pp;
        e1 += (i & 4) ? -pp : pp;
        e2 += (i & 2) ? -pp : pp;
        e3 += (i & 1) ? -pp : pp;
    }
    return make_float4(e0, e1, e2, e3);
}

__global__ __launch_bounds__(NTHR, 2)
void qconv_kernel(const float* __restrict__ x,     // (16,64,64,64)
                  const float* __restrict__ fc1w,  // (4,576)
                  const float* __restrict__ fc1b,  // (4,)
                  const float* __restrict__ u3p,   // (4,3)
                  const float* __restrict__ cu3p,  // (4,3)
                  const float* __restrict__ fcw,   // (128,4)
                  const float* __restrict__ fcb,   // (128,)
                  float* __restrict__ out)         // (16,4096,128) flat
{
    __shared__ float4 wq[576];            // packed conv weights (f32x2 pairs)
    __shared__ float4 xs4[2][2][HALO_N];  // [buf][chan-group][pos] 4 channels/float4
    __shared__ float4 ezd[TH * TW * 2];   // duplicated <Z>: (e0,e0,e1,e1)(e2,e2,e3,e3)
    __shared__ float  sgates[64];         // [0..31] U3, [32..63] CU3

    const int t  = threadIdx.x;
    const int b  = blockIdx.z;
    const int h0 = blockIdx.y * TH;
    const int w0 = blockIdx.x * TW;

    // ---- per-block setup ----
    if (t < 8) {
        const float* p = (t < 4) ? (u3p + t * 3) : (cu3p + (t - 4) * 3);
        float th = p[0], ph = p[1], la = p[2];
        float st, ct;   __sincosf(0.5f * th, &st, &ct);
        float sl, cl;   __sincosf(la, &sl, &cl);
        float sp, cp;   __sincosf(ph, &sp, &cp);
        float spl, cpl; __sincosf(ph + la, &spl, &cpl);
        float* o = sgates + t * 8;
        o[0] = ct;        o[1] = 0.f;
        o[2] = -cl * st;  o[3] = -sl * st;
        o[4] = cp * st;   o[5] = sp * st;
        o[6] = cpl * ct;  o[7] = spl * ct;
    }
    // wq[s*72 + tap*8 + p*2 + h] = (w[c0][2h], w[c1][2h], w[c0][2h+1], w[c1][2h+1])
    #pragma unroll
    for (int f = t; f < 576; f += NTHR) {
        int h   = f & 1;
        int p   = (f >> 1) & 3;
        int tap = (f >> 3) % 9;
        int s   = f / 72;
        int c0  = s * 8 + 2 * p;
        int oa  = 2 * h, ob = 2 * h + 1;
        wq[f] = make_float4(fc1w[oa * 576 + c0 * 9 + tap],
                            fc1w[oa * 576 + (c0 + 1) * 9 + tap],
                            fc1w[ob * 576 + c0 * 9 + tap],
                            fc1w[ob * 576 + (c0 + 1) * 9 + tap]);
    }

    const int ty = t >> 4;   // 0..7  (handles pixel rows 2ty, 2ty+1)
    const int tx = t & 15;   // 0..15
    const int by = h0 - 1, bx = w0 - 1;

    // ---- channel-invariant halo staging: 3 slots/thread over 324 positions ----
    const int i0 = t, i1 = t + NTHR, i2 = t + 2 * NTHR;
    const bool has2 = (i2 < HALO_N);
    const int r0 = i0 / HALO_W, c0s = i0 - r0 * HALO_W;
    const int r1 = i1 / HALO_W, c1s = i1 - r1 * HALO_W;
    const int r2 = has2 ? i2 / HALO_W : 0, c2s = has2 ? (i2 - r2 * HALO_W) : 0;

    int gy, gx;
    gy = by + r0; gx = bx + c0s;
    const bool va0 = (unsigned)gy < (unsigned)HH && (unsigned)gx < (unsigned)WW;
    const float* cur0 = x + ((size_t)b * CIN) * (HH * WW) + (va0 ? gy * WW + gx : 0);
    gy = by + r1; gx = bx + c1s;
    const bool va1 = (unsigned)gy < (unsigned)HH && (unsigned)gx < (unsigned)WW;
    const float* cur1 = x + ((size_t)b * CIN) * (HH * WW) + (va1 ? gy * WW + gx : 0);
    gy = by + r2; gx = bx + c2s;
    const bool va2 = has2 && (unsigned)gy < (unsigned)HH && (unsigned)gx < (unsigned)WW;
    const float* cur2 = x + ((size_t)b * CIN) * (HH * WW) + (va2 ? gy * WW + gx : 0);

    // Prologue: load channel-group 0 into registers.
    float v0[8], v1[8], v2[8];
    #pragma unroll
    for (int k = 0; k < 8; ++k) v0[k] = va0 ? cur0[k * (HH * WW)] : 0.f;
    #pragma unroll
    for (int k = 0; k < 8; ++k) v1[k] = va1 ? cur1[k * (HH * WW)] : 0.f;
    #pragma unroll
    for (int k = 0; k < 8; ++k) v2[k] = va2 ? cur2[k * (HH * WW)] : 0.f;
    cur0 += 8 * HH * WW; cur1 += 8 * HH * WW; cur2 += 8 * HH * WW;

    // 8 packed accumulators: A = pixel row 2ty, B = pixel row 2ty+1.
    unsigned long long A0, A1, A2, A3, B0, B1, B2, B3;
    {
        float z = 0.f;
        float b0 = fc1b[0], b1 = fc1b[1], b2 = fc1b[2], b3 = fc1b[3];
        PACK2(A0, b0, z); PACK2(A1, b1, z); PACK2(A2, b2, z); PACK2(A3, b3, z);
        PACK2(B0, b0, z); PACK2(B1, b1, z); PACK2(B2, b2, z); PACK2(B3, b3, z);
    }

    const int hbase = (2 * ty) * HALO_W + tx;

    // Double-buffered, ONE barrier per stage: STS(s) -> LDG(s+1) -> bar -> compute(s)
    for (int s = 0; s < 8; ++s) {
        {
            float4* d0 = xs4[s & 1][0];
            float4* d1 = xs4[s & 1][1];
            d0[i0] = make_float4(v0[0], v0[1], v0[2], v0[3]);
            d1[i0] = make_float4(v0[4], v0[5], v0[6], v0[7]);
            d0[i1] = make_float4(v1[0], v1[1], v1[2], v1[3]);
            d1[i1] = make_float4(v1[4], v1[5], v1[6], v1[7]);
            if (has2) {
                d0[i2] = make_float4(v2[0], v2[1], v2[2], v2[3]);
                d1[i2] = make_float4(v2[4], v2[5], v2[6], v2[7]);
            }
        }
        if (s < 7) {
            #pragma unroll
            for (int k = 0; k < 8; ++k) v0[k] = va0 ? cur0[k * (HH * WW)] : 0.f;
            #pragma unroll
            for (int k = 0; k < 8; ++k) v1[k] = va1 ? cur1[k * (HH * WW)] : 0.f;
            #pragma unroll
            for (int k = 0; k < 8; ++k) v2[k] = va2 ? cur2[k * (HH * WW)] : 0.f;
            cur0 += 8 * HH * WW; cur1 += 8 * HH * WW; cur2 += 8 * HH * WW;
        }
        __syncthreads();

        const ulonglong2* xg0 = (const ulonglong2*)xs4[s & 1][0];
        const ulonglong2* xg1 = (const ulonglong2*)xs4[s & 1][1];
        const ulonglong2* wp  = (const ulonglong2*)(wq + s * 72);

        #pragma unroll
        for (int dj = 0; dj < 3; ++dj) {
            ulonglong2 xlo[4], xhi[4];
            #pragma unroll
            for (int r = 0; r < 4; ++r) xlo[r] = xg0[hbase + dj + r * HALO_W];
            #pragma unroll
            for (int r = 0; r < 4; ++r) xhi[r] = xg1[hbase + dj + r * HALO_W];
            #pragma unroll
            for (int di = 0; di < 3; ++di) {
                const ulonglong2* wt = wp + (di * 3 + dj) * 8;
                ulonglong2 w0 = wt[0], w1 = wt[1], w2 = wt[2], w3 = wt[3];
                ulonglong2 w4 = wt[4], w5 = wt[5], w6 = wt[6], w7 = wt[7];
                FMA2(A0, xlo[di].x, w0.x); FMA2(A1, xlo[di].x, w0.y);
                FMA2(A2, xlo[di].x, w1.x); FMA2(A3, xlo[di].x, w1.y);
                FMA2(B0, xlo[di+1].x, w0.x); FMA2(B1, xlo[di+1].x, w0.y);
                FMA2(B2, xlo[di+1].x, w1.x); FMA2(B3, xlo[di+1].x, w1.y);
                FMA2(A0, xlo[di].y, w2.x); FMA2(A1, xlo[di].y, w2.y);
                FMA2(A2, xlo[di].y, w3.x); FMA2(A3, xlo[di].y, w3.y);
                FMA2(B0, xlo[di+1].y, w2.x); FMA2(B1, xlo[di+1].y, w2.y);
                FMA2(B2, xlo[di+1].y, w3.x); FMA2(B3, xlo[di+1].y, w3.y);
                FMA2(A0, xhi[di].x, w4.x); FMA2(A1, xhi[di].x, w4.y);
                FMA2(A2, xhi[di].x, w5.x); FMA2(A3, xhi[di].x, w5.y);
                FMA2(B0, xhi[di+1].x, w4.x); FMA2(B1, xhi[di+1].x, w4.y);
                FMA2(B2, xhi[di+1].x, w5.x); FMA2(B3, xhi[di+1].x, w5.y);
                FMA2(A0, xhi[di].y, w6.x); FMA2(A1, xhi[di].y, w6.y);
                FMA2(A2, xhi[di].y, w7.x); FMA2(A3, xhi[di].y, w7.y);
                FMA2(B0, xhi[di+1].y, w6.x); FMA2(B1, xhi[di+1].y, w6.y);
                FMA2(B2, xhi[di+1].y, w7.x); FMA2(B3, xhi[di+1].y, w7.y);
            }
        }
    }

    // Reduce packed accumulators -> angles, run circuit, store duplicated ez.
    {
        float lo, hi, a0, a1, a2, a3;
        asm("mov.b64 {%0, %1}, %2;" : "=f"(lo), "=f"(hi) : "l"(A0)); a0 = lo + hi;
        asm("mov.b64 {%0, %1}, %2;" : "=f"(lo), "=f"(hi) : "l"(A1)); a1 = lo + hi;
        asm("mov.b64 {%0, %1}, %2;" : "=f"(lo), "=f"(hi) : "l"(A2)); a2 = lo + hi;
        asm("mov.b64 {%0, %1}, %2;" : "=f"(lo), "=f"(hi) : "l"(A3)); a3 = lo + hi;
        float4 eA = quantum_ez(sgates, a0, a1, a2, a3);
        int lpA = (2 * ty) * TW + tx;
        ezd[lpA * 2 + 0] = make_float4(eA.x, eA.x, eA.y, eA.y);
        ezd[lpA * 2 + 1] = make_float4(eA.z, eA.z, eA.w, eA.w);
        asm("mov.b64 {%0, %1}, %2;" : "=f"(lo), "=f"(hi) : "l"(B0)); a0 = lo + hi;
        asm("mov.b64 {%0, %1}, %2;" : "=f"(lo), "=f"(hi) : "l"(B1)); a1 = lo + hi;
        asm("mov.b64 {%0, %1}, %2;" : "=f"(lo), "=f"(hi) : "l"(B2)); a2 = lo + hi;
        asm("mov.b64 {%0, %1}, %2;" : "=f"(lo), "=f"(hi) : "l"(B3)); a3 = lo + hi;
        float4 eB = quantum_ez(sgates, a0, a1, a2, a3);
        int lpB = (2 * ty + 1) * TW + tx;
        ezd[lpB * 2 + 0] = make_float4(eB.x, eB.x, eB.y, eB.y);
        ezd[lpB * 2 + 1] = make_float4(eB.z, eB.z, eB.w, eB.w);
    }
    __syncthreads();

    // ---------------- coalesced FC epilogue (f32x2-packed, no packs in loop) ----
    const int lane = t & 31;
    const int wi   = t >> 5;
    const float4* fw4 = (const float4*)fcw;
    float4 fr0 = fw4[4 * lane + 0];
    float4 fr1 = fw4[4 * lane + 1];
    float4 fr2 = fw4[4 * lane + 2];
    float4 fr3 = fw4[4 * lane + 3];
    float4 bb4 = ((const float4*)fcb)[lane];

    unsigned long long w01k0, w01k1, w01k2, w01k3;
    unsigned long long w23k0, w23k1, w23k2, w23k3;
    unsigned long long bias01, bias23;
    PACK2(w01k0, fr0.x, fr1.x); PACK2(w01k1, fr0.y, fr1.y);
    PACK2(w01k2, fr0.z, fr1.z); PACK2(w01k3, fr0.w, fr1.w);
    PACK2(w23k0, fr2.x, fr3.x); PACK2(w23k1, fr2.y, fr3.y);
    PACK2(w23k2, fr2.z, fr3.z); PACK2(w23k3, fr2.w, fr3.w);
    PACK2(bias01, bb4.x, bb4.y); PACK2(bias23, bb4.z, bb4.w);

    const ulonglong2* ezp = (const ulonglong2*)ezd;
    ulonglong2* ob = (ulonglong2*)out + (size_t)b * 4096 * 32;
    #pragma unroll 4
    for (int j = 0; j < 64; ++j) {
        const int lp = wi * 64 + j;
        ulonglong2 e01 = ezp[lp * 2 + 0];   // (e0,e0),(e1,e1)
        ulonglong2 e23 = ezp[lp * 2 + 1];   // (e2,e2),(e3,e3)
        unsigned long long acc01, acc23;
        FMA2N(acc01, w01k0, e01.x, bias01);
        FMA2N(acc23, w23k0, e01.x, bias23);
        FMA2(acc01, w01k1, e01.y); FMA2(acc23, w23k1, e01.y);
        FMA2(acc01, w01k2, e23.x); FMA2(acc23, w23k2, e23.x);
        FMA2(acc01, w01k3, e23.y); FMA2(acc23, w23k3, e23.y);
        const int py = h0 + (lp >> 4);
        const int px = w0 + (lp & 15);
        ulonglong2 o2; o2.x = acc01; o2.y = acc23;
        ob[(size_t)(py * WW + px) * 32 + lane] = o2;
    }
}

extern "C" void kernel_launch(void* const* d_in, const int* in_sizes, int n_in,
                              void* d_out, int out_size)
{
    (void)in_sizes; (void)n_in; (void)out_size;
    const float* x    = (const float*)d_in[0];
    const float* fc1w = (const float*)d_in[1];
    const float* fc1b = (const float*)d_in[2];
    const float* u3p  = (const float*)d_in[3];
    const float* cu3p = (const float*)d_in[4];
    const float* fcw  = (const float*)d_in[5];
    const float* fcb  = (const float*)d_in[6];
    float* out = (float*)d_out;

    dim3 grid(WW / TW, HH / TH, 16);
    qconv_kernel<<<grid, NTHR>>>(x, fc1w, fc1b, u3p, cu3p, fcw, fcb, out);
}